// round 1
// baseline (speedup 1.0000x reference)
#include <cuda_runtime.h>
#include <cstdint>
#include <math.h>

// Problem constants (shapes fixed by the dataset)
#define BATCH 8
#define LSEQ  1024            // H*W = 32*32
#define DIM   512
#define DI    1024            // 2*DIM
#define DS    16
#define DTR   32
#define HID   1024
#define ROWS  (BATCH*LSEQ)    // 8192

// ---------------- scratch (static device arrays; no allocs) ----------------
__device__ float g_pos_h  [LSEQ*DIM];
__device__ float g_pos    [LSEQ*DIM];
__device__ float g_pos_mix[LSEQ*DIM];
__device__ float g_scan_in[ROWS*DIM];
__device__ float g_xz     [ROWS*4096];        // [row, dir*2048 + {xin(0..1023), z(1024..2047)}]
__device__ float g_xc     [2*ROWS*DI];        // [dir, row, d]
__device__ float g_proj   [2*ROWS*64];        // [dir, row, {dt32,B16,C16}]
__device__ float g_dsp    [2*ROWS*DI];        // softplus(delta)
__device__ float g_ycat   [ROWS*2048];        // [row, dir*1024 + d]
__device__ float g_dmix   [ROWS*DIM];
__device__ float g_dln    [ROWS*DIM];
__device__ float g_lnf    [ROWS*DIM];
__device__ float g_h1     [ROWS*HID];
__device__ float g_wc     [DIM*2048];         // combined mix@out_w, [o, dir*1024 + e]

// ---------------- math helpers ----------------
__device__ __forceinline__ float geluf(float x) {
    return 0.5f * x * (1.0f + erff(x * 0.70710678118654752440f));
}
__device__ __forceinline__ float siluf(float x) {
    return x / (1.0f + __expf(-x));
}
__device__ __forceinline__ float softplusf(float x) {
    return (x > 20.0f) ? x : log1pf(__expf(x));
}

// ---------------- generic fp32 GEMM  C[m,n] = sum_k A[m,k] * B(n,k) ----------------
// TRANSB=true : B is (N,K) row-major (weight layout, computes A @ B^T)
// TRANSB=false: B is (K,N) row-major (computes A @ B)
// EPI: 0 none, 1 gelu, 2 silu, 3 softplus, 4 add aux[(m%auxMod)*N+n], 5 add aux[m*N+n]
// grid.z batches with element strides sA/sB/sC/sBias.
template<bool TRANSB, int EPI>
__global__ void __launch_bounds__(256)
sgemm(const float* __restrict__ A, int lda, long long sA,
      const float* __restrict__ B, int ldb, long long sB,
      float* __restrict__ C, int ldc, long long sC,
      const float* __restrict__ bias, long long sBias,
      const float* __restrict__ aux, int auxMod,
      int M, int N, int K)
{
    __shared__ float As[8][128];
    __shared__ float Bs[8][128];

    const int zi = blockIdx.z;
    A += (size_t)zi * sA;
    B += (size_t)zi * sB;
    C += (size_t)zi * sC;
    const float* bp = bias ? (bias + (size_t)zi * sBias) : nullptr;

    const int bm = blockIdx.y * 128;
    const int bn = blockIdx.x * 128;
    const int tid = threadIdx.x;
    const int tx = tid & 15;        // 0..15 (n)
    const int ty = tid >> 4;        // 0..15 (m)

    float acc[8][8];
#pragma unroll
    for (int i = 0; i < 8; i++)
#pragma unroll
        for (int j = 0; j < 8; j++) acc[i][j] = 0.0f;

    const int arow = tid >> 1;           // 0..127
    const int acol = (tid & 1) << 2;     // 0 or 4

    for (int k0 = 0; k0 < K; k0 += 8) {
        // A tile (M always a multiple of 128 in this problem; K multiple of 8, lda%4==0)
        float4 av = *(const float4*)(A + (size_t)(bm + arow) * lda + k0 + acol);
        As[acol + 0][arow] = av.x;
        As[acol + 1][arow] = av.y;
        As[acol + 2][arow] = av.z;
        As[acol + 3][arow] = av.w;

        if (TRANSB) {
            const int nl = tid >> 1;
            float4 bv = make_float4(0.f, 0.f, 0.f, 0.f);
            if (bn + nl < N)
                bv = *(const float4*)(B + (size_t)(bn + nl) * ldb + k0 + acol);
            Bs[acol + 0][nl] = bv.x;
            Bs[acol + 1][nl] = bv.y;
            Bs[acol + 2][nl] = bv.z;
            Bs[acol + 3][nl] = bv.w;
        } else {
            const int kl = tid >> 5;             // 0..7
            const int nl = (tid & 31) << 2;      // 0..124
            float4 bv = make_float4(0.f, 0.f, 0.f, 0.f);
            if (bn + nl < N)
                bv = *(const float4*)(B + (size_t)(k0 + kl) * ldb + bn + nl);
            *(float4*)&Bs[kl][nl] = bv;
        }
        __syncthreads();

#pragma unroll
        for (int k = 0; k < 8; k++) {
            float a[8], b[8];
            *(float4*)(a)     = *(const float4*)&As[k][ty * 8];
            *(float4*)(a + 4) = *(const float4*)&As[k][ty * 8 + 4];
            *(float4*)(b)     = *(const float4*)&Bs[k][tx * 8];
            *(float4*)(b + 4) = *(const float4*)&Bs[k][tx * 8 + 4];
#pragma unroll
            for (int i = 0; i < 8; i++)
#pragma unroll
                for (int j = 0; j < 8; j++)
                    acc[i][j] = fmaf(a[i], b[j], acc[i][j]);
        }
        __syncthreads();
    }

#pragma unroll
    for (int i = 0; i < 8; i++) {
        const int m = bm + ty * 8 + i;
#pragma unroll
        for (int j = 0; j < 8; j++) {
            const int n = bn + tx * 8 + j;
            if (n < N) {
                float v = acc[i][j];
                if (bp) v += bp[n];
                if (EPI == 1)      v = geluf(v);
                else if (EPI == 2) v = siluf(v);
                else if (EPI == 3) v = softplusf(v);
                else if (EPI == 4) v += aux[(size_t)(m % auxMod) * N + n];
                else if (EPI == 5) v += aux[(size_t)m * N + n];
                C[(size_t)m * ldc + n] = v;
            }
        }
    }
}

// ---------------- positional features: gelu(pos6 @ w1^T + b1) ----------------
__global__ void pos_hidden_k(const float* __restrict__ w1, const float* __restrict__ b1,
                             float* __restrict__ ph)
{
    int idx = blockIdx.x * 256 + threadIdx.x;
    if (idx >= LSEQ * DIM) return;
    int t = idx >> 9;       // /512
    int c = idx & 511;
    int y = t >> 5, x = t & 31;
    const float PI = 3.14159265358979323846f;
    float yy = ((y + 0.5f) / 32.0f) * 2.0f - 1.0f;
    float xx = ((x + 0.5f) / 32.0f) * 2.0f - 1.0f;
    float f2 = sinf(PI * yy), f3 = cosf(PI * yy);
    float f4 = sinf(PI * xx), f5 = cosf(PI * xx);
    const float* w = w1 + c * 6;
    float v = b1[c] + yy * w[0] + xx * w[1] + f2 * w[2] + f3 * w[3] + f4 * w[4] + f5 * w[5];
    ph[idx] = geluf(v);
}

// ---------------- LN(tokens) + pos ----------------
__global__ void ln_add_pos_k(const float* __restrict__ x,
                             const float* __restrict__ g, const float* __restrict__ b,
                             const float* __restrict__ pos, float* __restrict__ out)
{
    __shared__ float sh[32];
    const int row = blockIdx.x;
    const int tid = threadIdx.x;   // 256
    const float* xr = x + (size_t)row * DIM;
    float v0 = xr[tid], v1 = xr[tid + 256];

    float s = v0 + v1, q = v0 * v0 + v1 * v1;
#pragma unroll
    for (int o = 16; o; o >>= 1) {
        s += __shfl_xor_sync(0xffffffffu, s, o);
        q += __shfl_xor_sync(0xffffffffu, q, o);
    }
    if ((tid & 31) == 0) { sh[tid >> 5] = s; sh[8 + (tid >> 5)] = q; }
    __syncthreads();
    if (tid == 0) {
        float S = 0.f, Q = 0.f;
        for (int i = 0; i < 8; i++) { S += sh[i]; Q += sh[8 + i]; }
        float mu = S * (1.0f / DIM);
        float var = Q * (1.0f / DIM) - mu * mu;
        sh[16] = mu; sh[17] = rsqrtf(var + 1e-5f);
    }
    __syncthreads();
    const float mu = sh[16], rs = sh[17];
    const int t = row & (LSEQ - 1);
    const float* pr = pos + (size_t)t * DIM;
    float* orow = out + (size_t)row * DIM;
    orow[tid]       = (v0 - mu) * rs * g[tid]       + b[tid]       + pr[tid];
    orow[tid + 256] = (v1 - mu) * rs * g[tid + 256] + b[tid + 256] + pr[tid + 256];
}

// ---------------- causal conv (dir-aware) + SiLU ----------------
__global__ void conv_silu_k(const float* __restrict__ xz,
                            const float* __restrict__ cw, const float* __restrict__ cb,
                            float* __restrict__ xc)
{
    size_t idx = (size_t)blockIdx.x * 256 + threadIdx.x;  // 2*ROWS*DI total
    int d   = (int)(idx & 1023);
    int row = (int)((idx >> 10) & (ROWS - 1));
    int dir = (int)(idx >> 23);
    int t = row & (LSEQ - 1);
    int b = row >> 10;

    float acc = cb[dir * DI + d];
#pragma unroll
    for (int k = 0; k < 4; k++) {
        int off = dir ? (3 - k) : (k - 3);
        int tt = t + off;
        if (tt >= 0 && tt < LSEQ) {
            float v = xz[((size_t)(b * LSEQ + tt)) * 4096 + dir * 2048 + d];
            acc = fmaf(cw[(dir * DI + d) * 4 + k], v, acc);
        }
    }
    xc[idx] = siluf(acc);
}

// ---------------- selective scan ----------------
// grid: (DI/128, BATCH, 2), block 128; one thread per channel; 16 states in regs.
__global__ void scan_k(const float* __restrict__ dsp, const float* __restrict__ xc,
                       const float* __restrict__ proj, const float* __restrict__ xz,
                       const float* __restrict__ A_log, const float* __restrict__ Dp,
                       float* __restrict__ ycat)
{
    const int dir = blockIdx.z;
    const int b   = blockIdx.y;
    const int d   = blockIdx.x * 128 + threadIdx.x;

    float a[DS];
#pragma unroll
    for (int s = 0; s < DS; s++)
        a[s] = -expf(A_log[((size_t)dir * DI + d) * DS + s]);
    const float Dv = Dp[dir * DI + d];

    float h[DS];
#pragma unroll
    for (int s = 0; s < DS; s++) h[s] = 0.0f;

    const size_t base_row = (size_t)dir * ROWS + (size_t)b * LSEQ;
    __shared__ float sBC[64][32];

    for (int tc = 0; tc < LSEQ; tc += 64) {
        __syncthreads();
        for (int i = threadIdx.x; i < 64 * 32; i += 128) {
            int step = tc + (i >> 5);
            int c = i & 31;
            int r = dir ? (LSEQ - 1 - step) : step;
            sBC[i >> 5][c] = proj[(base_row + r) * 64 + 32 + c];
        }
        __syncthreads();

        for (int i = 0; i < 64; i++) {
            int step = tc + i;
            int r = dir ? (LSEQ - 1 - step) : step;
            size_t ro = (base_row + r) * (size_t)DI + d;
            float delta = dsp[ro];
            float x     = xc[ro];
            float dx    = delta * x;
            float y = 0.0f;
#pragma unroll
            for (int s = 0; s < DS; s++) {
                float e = __expf(delta * a[s]);
                h[s] = fmaf(h[s], e, dx * sBC[i][s]);
                y = fmaf(h[s], sBC[i][16 + s], y);
            }
            float z = xz[((size_t)(b * LSEQ + r)) * 4096 + dir * 2048 + DI + d];
            float outv = (y + x * Dv) * siluf(z);
            ycat[((size_t)(b * LSEQ + r)) * 2048 + dir * DI + d] = outv;
        }
    }
}

// ---------------- dual LayerNorm: out1 = LN(in; g1,b1), out2 = LN(out1; g2,b2) ----------------
__global__ void ln_dual_k(const float* __restrict__ in,
                          const float* __restrict__ g1, const float* __restrict__ b1,
                          const float* __restrict__ g2, const float* __restrict__ b2,
                          float* __restrict__ out1, float* __restrict__ out2)
{
    __shared__ float sh[32];
    const int row = blockIdx.x;
    const int tid = threadIdx.x;
    const float* xr = in + (size_t)row * DIM;
    float v0 = xr[tid], v1 = xr[tid + 256];

    float s = v0 + v1, q = v0 * v0 + v1 * v1;
#pragma unroll
    for (int o = 16; o; o >>= 1) {
        s += __shfl_xor_sync(0xffffffffu, s, o);
        q += __shfl_xor_sync(0xffffffffu, q, o);
    }
    if ((tid & 31) == 0) { sh[tid >> 5] = s; sh[8 + (tid >> 5)] = q; }
    __syncthreads();
    if (tid == 0) {
        float S = 0.f, Q = 0.f;
        for (int i = 0; i < 8; i++) { S += sh[i]; Q += sh[8 + i]; }
        float mu = S * (1.0f / DIM);
        float var = Q * (1.0f / DIM) - mu * mu;
        sh[16] = mu; sh[17] = rsqrtf(var + 1e-5f);
    }
    __syncthreads();
    float mu = sh[16], rs = sh[17];
    float x0 = (v0 - mu) * rs * g1[tid]       + b1[tid];
    float x1 = (v1 - mu) * rs * g1[tid + 256] + b1[tid + 256];
    float* o1 = out1 + (size_t)row * DIM;
    o1[tid] = x0; o1[tid + 256] = x1;

    __syncthreads();
    s = x0 + x1; q = x0 * x0 + x1 * x1;
#pragma unroll
    for (int o = 16; o; o >>= 1) {
        s += __shfl_xor_sync(0xffffffffu, s, o);
        q += __shfl_xor_sync(0xffffffffu, q, o);
    }
    if ((tid & 31) == 0) { sh[tid >> 5] = s; sh[8 + (tid >> 5)] = q; }
    __syncthreads();
    if (tid == 0) {
        float S = 0.f, Q = 0.f;
        for (int i = 0; i < 8; i++) { S += sh[i]; Q += sh[8 + i]; }
        float mu2 = S * (1.0f / DIM);
        float var2 = Q * (1.0f / DIM) - mu2 * mu2;
        sh[16] = mu2; sh[17] = rsqrtf(var2 + 1e-5f);
    }
    __syncthreads();
    float mu2 = sh[16], rs2 = sh[17];
    float* o2 = out2 + (size_t)row * DIM;
    o2[tid]       = (x0 - mu2) * rs2 * g2[tid]       + b2[tid];
    o2[tid + 256] = (x1 - mu2) * rs2 * g2[tid + 256] + b2[tid + 256];
}

// ---------------- host launcher ----------------
extern "C" void kernel_launch(void* const* d_in, const int* in_sizes, int n_in,
                              void* d_out, int out_size)
{
    const float* tokens    = (const float*)d_in[0];
    const float* in_g      = (const float*)d_in[3];
    const float* in_b      = (const float*)d_in[4];
    const float* pos_w1    = (const float*)d_in[5];
    const float* pos_b1    = (const float*)d_in[6];
    const float* pos_w2    = (const float*)d_in[7];
    const float* pos_b2    = (const float*)d_in[8];
    const float* m_in_w    = (const float*)d_in[9];
    const float* m_conv_w  = (const float*)d_in[10];
    const float* m_conv_b  = (const float*)d_in[11];
    const float* m_xproj_w = (const float*)d_in[12];
    const float* m_dt_w    = (const float*)d_in[13];
    const float* m_dt_b    = (const float*)d_in[14];
    const float* m_A_log   = (const float*)d_in[15];
    const float* m_D       = (const float*)d_in[16];
    const float* m_out_w   = (const float*)d_in[17];
    const float* mix_w     = (const float*)d_in[18];
    const float* mix_b     = (const float*)d_in[19];
    const float* dn_g      = (const float*)d_in[20];
    const float* dn_b      = (const float*)d_in[21];
    const float* fn_g      = (const float*)d_in[22];
    const float* fn_b      = (const float*)d_in[23];
    const float* ffn_w1    = (const float*)d_in[24];
    const float* ffn_b1    = (const float*)d_in[25];
    const float* ffn_w2    = (const float*)d_in[26];
    const float* ffn_b2    = (const float*)d_in[27];
    float* out = (float*)d_out;

    float *pos_h, *pos, *pos_mix, *scan_in, *xz, *xc, *proj, *dsp, *ycat, *dmix, *dln, *lnf, *h1, *wc;
    cudaGetSymbolAddress((void**)&pos_h,   g_pos_h);
    cudaGetSymbolAddress((void**)&pos,     g_pos);
    cudaGetSymbolAddress((void**)&pos_mix, g_pos_mix);
    cudaGetSymbolAddress((void**)&scan_in, g_scan_in);
    cudaGetSymbolAddress((void**)&xz,      g_xz);
    cudaGetSymbolAddress((void**)&xc,      g_xc);
    cudaGetSymbolAddress((void**)&proj,    g_proj);
    cudaGetSymbolAddress((void**)&dsp,     g_dsp);
    cudaGetSymbolAddress((void**)&ycat,    g_ycat);
    cudaGetSymbolAddress((void**)&dmix,    g_dmix);
    cudaGetSymbolAddress((void**)&dln,     g_dln);
    cudaGetSymbolAddress((void**)&lnf,     g_lnf);
    cudaGetSymbolAddress((void**)&h1,      g_h1);
    cudaGetSymbolAddress((void**)&wc,      g_wc);

    // pos pipeline
    pos_hidden_k<<<(LSEQ * DIM) / 256, 256>>>(pos_w1, pos_b1, pos_h);
    sgemm<true, 0><<<dim3(4, 8, 1), 256>>>(pos_h, 512, 0, pos_w2, 512, 0,
                                           pos, 512, 0, pos_b2, 0, nullptr, 1,
                                           1024, 512, 512);
    // pos_mix = pos @ mix_w[:,1024:1536]^T + mix_b
    sgemm<true, 0><<<dim3(4, 8, 1), 256>>>(pos, 512, 0, mix_w + 1024, 1536, 0,
                                           pos_mix, 512, 0, mix_b, 0, nullptr, 1,
                                           1024, 512, 512);
    // Wc[dir] = mix_w[:, dir*512:(dir+1)*512] @ out_w[dir]   (512 x 1024), packed into (512, 2048)
    sgemm<false, 0><<<dim3(8, 4, 2), 256>>>(mix_w, 1536, 512, m_out_w, 1024, (long long)512 * 1024,
                                            wc, 2048, 1024, nullptr, 0, nullptr, 1,
                                            512, 1024, 512);
    // scan_in = LN(tokens) + pos
    ln_add_pos_k<<<ROWS, 256>>>(tokens, in_g, in_b, pos, scan_in);
    // xz = scan_in @ in_w_all^T   (both directions fused, N=4096)
    sgemm<true, 0><<<dim3(32, 64, 1), 256>>>(scan_in, 512, 0, m_in_w, 512, 0,
                                             xz, 4096, 0, nullptr, 0, nullptr, 1,
                                             ROWS, 4096, 512);
    // conv + silu
    conv_silu_k<<<(2 * ROWS * DI) / 256, 256>>>(xz, m_conv_w, m_conv_b, xc);
    // proj = xc @ xproj^T  (per dir)
    sgemm<true, 0><<<dim3(1, 64, 2), 256>>>(xc, 1024, (long long)ROWS * DI,
                                            m_xproj_w, 1024, (long long)64 * 1024,
                                            proj, 64, (long long)ROWS * 64,
                                            nullptr, 0, nullptr, 1,
                                            ROWS, 64, 1024);
    // dsp = softplus(dt @ dt_w^T + dt_b)  (per dir)
    sgemm<true, 3><<<dim3(8, 64, 2), 256>>>(proj, 64, (long long)ROWS * 64,
                                            m_dt_w, 32, (long long)1024 * 32,
                                            dsp, 1024, (long long)ROWS * DI,
                                            m_dt_b, 1024, nullptr, 1,
                                            ROWS, 1024, 32);
    // selective scan + gating → ycat
    scan_k<<<dim3(DI / 128, BATCH, 2), 128>>>(dsp, xc, proj, xz, m_A_log, m_D, ycat);
    // dmix = ycat @ Wc^T + pos_mix(broadcast over batch)
    sgemm<true, 4><<<dim3(4, 64, 1), 256>>>(ycat, 2048, 0, wc, 2048, 0,
                                            dmix, 512, 0, nullptr, 0, pos_mix, LSEQ,
                                            ROWS, 512, 2048);
    // dln = LN(dmix; dn),  lnf = LN(dln; fn)
    ln_dual_k<<<ROWS, 256>>>(dmix, dn_g, dn_b, fn_g, fn_b, dln, lnf);
    // h1 = gelu(lnf @ ffn_w1^T + b1)
    sgemm<true, 1><<<dim3(8, 64, 1), 256>>>(lnf, 512, 0, ffn_w1, 512, 0,
                                            h1, 1024, 0, ffn_b1, 0, nullptr, 1,
                                            ROWS, 1024, 512);
    // out = dln + h1 @ ffn_w2^T + b2
    sgemm<true, 5><<<dim3(4, 64, 1), 256>>>(h1, 1024, 0, ffn_w2, 1024, 0,
                                            out, 512, 0, ffn_b2, 0, dln, 1,
                                            ROWS, 512, 1024);
    (void)in_sizes; (void)n_in; (void)out_size;
}

// round 2
// speedup vs baseline: 1.6201x; 1.6201x over previous
#include <cuda_runtime.h>
#include <cuda_bf16.h>
#include <cstdint>
#include <math.h>

// Problem constants (shapes fixed by the dataset)
#define BATCH 8
#define LSEQ  1024            // H*W = 32*32
#define DIM   512
#define DI    1024            // 2*DIM
#define DS    16
#define DTR   32
#define HID   1024
#define ROWS  (BATCH*LSEQ)    // 8192

// ---------------- scratch (static device arrays; no allocs) ----------------
__device__ float g_pos_h  [LSEQ*DIM];
__device__ float g_pos    [LSEQ*DIM];
__device__ float g_pos_mix[LSEQ*DIM];
__device__ float g_scan_in[ROWS*DIM];
__device__ float g_xz     [ROWS*4096];        // [row, dir*2048 + {xin(0..1023), z(1024..2047)}]
__device__ float g_xc     [2*ROWS*DI];        // [dir, row, d]
__device__ float g_proj   [2*ROWS*64];        // [dir, row, {dt32,B16,C16}]
__device__ float g_dsp    [2*ROWS*DI];        // softplus(delta)
__device__ float g_ycat   [ROWS*2048];        // [row, dir*1024 + d]
__device__ float g_dmix   [ROWS*DIM];
__device__ float g_dln    [ROWS*DIM];
__device__ float g_lnf    [ROWS*DIM];
__device__ float g_h1     [ROWS*HID];
__device__ float g_wc     [DIM*2048];         // combined mix@out_w, [o, dir*1024 + e]

// ---------------- math helpers ----------------
__device__ __forceinline__ float geluf(float x) {
    return 0.5f * x * (1.0f + erff(x * 0.70710678118654752440f));
}
__device__ __forceinline__ float siluf(float x) {
    return x / (1.0f + __expf(-x));
}
__device__ __forceinline__ float softplusf(float x) {
    return (x > 20.0f) ? x : log1pf(__expf(x));
}

// ---------------- bf16 mma helper ----------------
__device__ __forceinline__ void mma16816(float& d0, float& d1, float& d2, float& d3,
                                         uint32_t a0, uint32_t a1, uint32_t a2, uint32_t a3,
                                         uint32_t b0, uint32_t b1)
{
    asm volatile(
        "mma.sync.aligned.m16n8k16.row.col.f32.bf16.bf16.f32 "
        "{%0,%1,%2,%3},{%4,%5,%6,%7},{%8,%9},{%0,%1,%2,%3};\n"
        : "+f"(d0), "+f"(d1), "+f"(d2), "+f"(d3)
        : "r"(a0), "r"(a1), "r"(a2), "r"(a3), "r"(b0), "r"(b1));
}

// ---------------- tensor-core GEMM (3-term bf16 split ≈ fp32 accuracy) ----------------
// C[m,n] = sum_k A[m,k] * B(n,k)
// TRANSB=true : B is (N,K) row-major (computes A @ B^T)
// TRANSB=false: B is (K,N) row-major (computes A @ B)
// EPI: 0 none, 1 gelu, 3 softplus, 4 add aux[(m%auxMod)*ldc+n], 5 add aux[m*ldc+n]
// Requirements: M % 128 == 0, K % 16 == 0, A/B rows 16B-aligned (true for all uses).
template<bool TRANSB, int EPI>
__global__ void __launch_bounds__(256)
bgemm(const float* __restrict__ A, int lda, long long sA,
      const float* __restrict__ B, int ldb, long long sB,
      float* __restrict__ C, int ldc, long long sC,
      const float* __restrict__ bias, long long sBias,
      const float* __restrict__ aux, int auxMod,
      int M, int N, int K)
{
    // 2 stages x (A,B) x (hi,lo), 128 rows x 16 cols, padded to 24 (48B rows).
    __shared__ __nv_bfloat16 Ah[2][128][24];
    __shared__ __nv_bfloat16 Al[2][128][24];
    __shared__ __nv_bfloat16 Bh[2][128][24];
    __shared__ __nv_bfloat16 Bl[2][128][24];

    const int zi = blockIdx.z;
    A += (size_t)zi * sA;
    B += (size_t)zi * sB;
    C += (size_t)zi * sC;
    const float* bp = bias ? (bias + (size_t)zi * sBias) : nullptr;

    const int bm = blockIdx.y * 128;
    const int bn = blockIdx.x * 128;
    const int tid  = threadIdx.x;
    const int lane = tid & 31;
    const int warp = tid >> 5;
    const int wm = warp & 1;      // 2 warps over M (64 each)
    const int wn = warp >> 1;     // 4 warps over N (32 each)
    const int r = lane >> 2;      // 0..7
    const int c = lane & 3;       // 0..3

    // global-load mapping
    const int aRow = tid >> 1;            // 0..127
    const int aKb  = (tid & 1) * 8;       // 0 or 8
    // TRANSB=false B mapping
    const int bnl  = tid & 127;
    const int bkl  = (tid >> 7) * 8;

    float areg[8], breg[8];

    auto loadAB = [&](int k0) {
        const float* ap = A + (size_t)(bm + aRow) * lda + k0 + aKb;
        float4 a0 = *(const float4*)ap;
        float4 a1 = *(const float4*)(ap + 4);
        areg[0] = a0.x; areg[1] = a0.y; areg[2] = a0.z; areg[3] = a0.w;
        areg[4] = a1.x; areg[5] = a1.y; areg[6] = a1.z; areg[7] = a1.w;
        if (TRANSB) {
            const int n = bn + aRow;
            if (n < N) {
                const float* bpr = B + (size_t)n * ldb + k0 + aKb;
                float4 b0 = *(const float4*)bpr;
                float4 b1 = *(const float4*)(bpr + 4);
                breg[0] = b0.x; breg[1] = b0.y; breg[2] = b0.z; breg[3] = b0.w;
                breg[4] = b1.x; breg[5] = b1.y; breg[6] = b1.z; breg[7] = b1.w;
            } else {
#pragma unroll
                for (int j = 0; j < 8; j++) breg[j] = 0.0f;
            }
        } else {
            const bool ok = (bn + bnl) < N;
#pragma unroll
            for (int j = 0; j < 8; j++)
                breg[j] = ok ? B[(size_t)(k0 + bkl + j) * ldb + bn + bnl] : 0.0f;
        }
    };

    auto stage = [&](int buf) {
        // A: row aRow, cols aKb..aKb+7
        __nv_bfloat162* pAh = (__nv_bfloat162*)&Ah[buf][aRow][aKb];
        __nv_bfloat162* pAl = (__nv_bfloat162*)&Al[buf][aRow][aKb];
#pragma unroll
        for (int j2 = 0; j2 < 4; j2++) {
            float v0 = areg[2 * j2], v1 = areg[2 * j2 + 1];
            __nv_bfloat16 h0 = __float2bfloat16(v0);
            __nv_bfloat16 h1 = __float2bfloat16(v1);
            __nv_bfloat16 l0 = __float2bfloat16(v0 - __bfloat162float(h0));
            __nv_bfloat16 l1 = __float2bfloat16(v1 - __bfloat162float(h1));
            __nv_bfloat162 hv; hv.x = h0; hv.y = h1;
            __nv_bfloat162 lv; lv.x = l0; lv.y = l1;
            pAh[j2] = hv; pAl[j2] = lv;
        }
        const int brow = TRANSB ? aRow : bnl;
        const int bkb  = TRANSB ? aKb  : bkl;
        __nv_bfloat162* pBh = (__nv_bfloat162*)&Bh[buf][brow][bkb];
        __nv_bfloat162* pBl = (__nv_bfloat162*)&Bl[buf][brow][bkb];
#pragma unroll
        for (int j2 = 0; j2 < 4; j2++) {
            float v0 = breg[2 * j2], v1 = breg[2 * j2 + 1];
            __nv_bfloat16 h0 = __float2bfloat16(v0);
            __nv_bfloat16 h1 = __float2bfloat16(v1);
            __nv_bfloat16 l0 = __float2bfloat16(v0 - __bfloat162float(h0));
            __nv_bfloat16 l1 = __float2bfloat16(v1 - __bfloat162float(h1));
            __nv_bfloat162 hv; hv.x = h0; hv.y = h1;
            __nv_bfloat162 lv; lv.x = l0; lv.y = l1;
            pBh[j2] = hv; pBl[j2] = lv;
        }
    };

    float acc[4][4][4];
#pragma unroll
    for (int i = 0; i < 4; i++)
#pragma unroll
        for (int j = 0; j < 4; j++)
#pragma unroll
            for (int q = 0; q < 4; q++) acc[i][j][q] = 0.0f;

    loadAB(0);
    stage(0);
    __syncthreads();

    const int nk = K / 16;
    for (int kt = 0; kt < nk; kt++) {
        const int cur = kt & 1;
        if (kt + 1 < nk) loadAB((kt + 1) * 16);

        const uint32_t* pAh = (const uint32_t*)&Ah[cur][0][0];
        const uint32_t* pAl = (const uint32_t*)&Al[cur][0][0];
        const uint32_t* pBh = (const uint32_t*)&Bh[cur][0][0];
        const uint32_t* pBl = (const uint32_t*)&Bl[cur][0][0];

        uint32_t ah[4][4], al[4][4];
#pragma unroll
        for (int mt = 0; mt < 4; mt++) {
            const int m = wm * 64 + mt * 16 + r;
            const int i0 = m * 12 + c;
            const int i1 = (m + 8) * 12 + c;
            ah[mt][0] = pAh[i0];     ah[mt][1] = pAh[i1];
            ah[mt][2] = pAh[i0 + 4]; ah[mt][3] = pAh[i1 + 4];
            al[mt][0] = pAl[i0];     al[mt][1] = pAl[i1];
            al[mt][2] = pAl[i0 + 4]; al[mt][3] = pAl[i1 + 4];
        }
#pragma unroll
        for (int nt = 0; nt < 4; nt++) {
            const int n = wn * 32 + nt * 8 + r;
            const int ib = n * 12 + c;
            uint32_t bh0 = pBh[ib], bh1 = pBh[ib + 4];
            uint32_t bl0 = pBl[ib], bl1 = pBl[ib + 4];
#pragma unroll
            for (int mt = 0; mt < 4; mt++) {
                float* d = acc[mt][nt];
                mma16816(d[0], d[1], d[2], d[3], ah[mt][0], ah[mt][1], ah[mt][2], ah[mt][3], bh0, bh1);
                mma16816(d[0], d[1], d[2], d[3], ah[mt][0], ah[mt][1], ah[mt][2], ah[mt][3], bl0, bl1);
                mma16816(d[0], d[1], d[2], d[3], al[mt][0], al[mt][1], al[mt][2], al[mt][3], bh0, bh1);
            }
        }

        if (kt + 1 < nk) stage(cur ^ 1);
        __syncthreads();
    }

    // epilogue
#pragma unroll
    for (int mt = 0; mt < 4; mt++) {
        const int m0 = bm + wm * 64 + mt * 16 + r;
#pragma unroll
        for (int nt = 0; nt < 4; nt++) {
            const int n0 = bn + wn * 32 + nt * 8 + 2 * c;
#pragma unroll
            for (int half = 0; half < 2; half++) {
                const int m = m0 + half * 8;
#pragma unroll
                for (int q = 0; q < 2; q++) {
                    const int n = n0 + q;
                    if (n < N) {
                        float v = acc[mt][nt][half * 2 + q];
                        if (bp) v += bp[n];
                        if (EPI == 1)      v = geluf(v);
                        else if (EPI == 3) v = softplusf(v);
                        else if (EPI == 4) v += aux[(size_t)(m % auxMod) * ldc + n];
                        else if (EPI == 5) v += aux[(size_t)m * ldc + n];
                        C[(size_t)m * ldc + n] = v;
                    }
                }
            }
        }
    }
}

// ---------------- positional features: gelu(pos6 @ w1^T + b1) ----------------
__global__ void pos_hidden_k(const float* __restrict__ w1, const float* __restrict__ b1,
                             float* __restrict__ ph)
{
    int idx = blockIdx.x * 256 + threadIdx.x;
    if (idx >= LSEQ * DIM) return;
    int t = idx >> 9;       // /512
    int c = idx & 511;
    int y = t >> 5, x = t & 31;
    const float PI = 3.14159265358979323846f;
    float yy = ((y + 0.5f) / 32.0f) * 2.0f - 1.0f;
    float xx = ((x + 0.5f) / 32.0f) * 2.0f - 1.0f;
    float f2 = sinf(PI * yy), f3 = cosf(PI * yy);
    float f4 = sinf(PI * xx), f5 = cosf(PI * xx);
    const float* w = w1 + c * 6;
    float v = b1[c] + yy * w[0] + xx * w[1] + f2 * w[2] + f3 * w[3] + f4 * w[4] + f5 * w[5];
    ph[idx] = geluf(v);
}

// ---------------- LN(tokens) + pos ----------------
__global__ void ln_add_pos_k(const float* __restrict__ x,
                             const float* __restrict__ g, const float* __restrict__ b,
                             const float* __restrict__ pos, float* __restrict__ out)
{
    __shared__ float sh[32];
    const int row = blockIdx.x;
    const int tid = threadIdx.x;   // 256
    const float* xr = x + (size_t)row * DIM;
    float v0 = xr[tid], v1 = xr[tid + 256];

    float s = v0 + v1, q = v0 * v0 + v1 * v1;
#pragma unroll
    for (int o = 16; o; o >>= 1) {
        s += __shfl_xor_sync(0xffffffffu, s, o);
        q += __shfl_xor_sync(0xffffffffu, q, o);
    }
    if ((tid & 31) == 0) { sh[tid >> 5] = s; sh[8 + (tid >> 5)] = q; }
    __syncthreads();
    if (tid == 0) {
        float S = 0.f, Q = 0.f;
        for (int i = 0; i < 8; i++) { S += sh[i]; Q += sh[8 + i]; }
        float mu = S * (1.0f / DIM);
        float var = Q * (1.0f / DIM) - mu * mu;
        sh[16] = mu; sh[17] = rsqrtf(var + 1e-5f);
    }
    __syncthreads();
    const float mu = sh[16], rs = sh[17];
    const int t = row & (LSEQ - 1);
    const float* pr = pos + (size_t)t * DIM;
    float* orow = out + (size_t)row * DIM;
    orow[tid]       = (v0 - mu) * rs * g[tid]       + b[tid]       + pr[tid];
    orow[tid + 256] = (v1 - mu) * rs * g[tid + 256] + b[tid + 256] + pr[tid + 256];
}

// ---------------- causal conv (dir-aware) + SiLU ----------------
__global__ void conv_silu_k(const float* __restrict__ xz,
                            const float* __restrict__ cw, const float* __restrict__ cb,
                            float* __restrict__ xc)
{
    size_t idx = (size_t)blockIdx.x * 256 + threadIdx.x;  // 2*ROWS*DI total
    int d   = (int)(idx & 1023);
    int row = (int)((idx >> 10) & (ROWS - 1));
    int dir = (int)(idx >> 23);
    int t = row & (LSEQ - 1);
    int b = row >> 10;

    float acc = cb[dir * DI + d];
#pragma unroll
    for (int k = 0; k < 4; k++) {
        int off = dir ? (3 - k) : (k - 3);
        int tt = t + off;
        if (tt >= 0 && tt < LSEQ) {
            float v = xz[((size_t)(b * LSEQ + tt)) * 4096 + dir * 2048 + d];
            acc = fmaf(cw[(dir * DI + d) * 4 + k], v, acc);
        }
    }
    xc[idx] = siluf(acc);
}

// ---------------- selective scan ----------------
// grid: (DI/128, BATCH, 2), block 128; one thread per channel; 16 states in regs.
__global__ void scan_k(const float* __restrict__ dsp, const float* __restrict__ xc,
                       const float* __restrict__ proj, const float* __restrict__ xz,
                       const float* __restrict__ A_log, const float* __restrict__ Dp,
                       float* __restrict__ ycat)
{
    const int dir = blockIdx.z;
    const int b   = blockIdx.y;
    const int d   = blockIdx.x * 128 + threadIdx.x;

    float a[DS];
#pragma unroll
    for (int s = 0; s < DS; s++)
        a[s] = -expf(A_log[((size_t)dir * DI + d) * DS + s]);
    const float Dv = Dp[dir * DI + d];

    float h[DS];
#pragma unroll
    for (int s = 0; s < DS; s++) h[s] = 0.0f;

    const size_t base_row = (size_t)dir * ROWS + (size_t)b * LSEQ;
    __shared__ float sBC[64][32];

    for (int tc = 0; tc < LSEQ; tc += 64) {
        __syncthreads();
        for (int i = threadIdx.x; i < 64 * 32; i += 128) {
            int step = tc + (i >> 5);
            int c = i & 31;
            int r = dir ? (LSEQ - 1 - step) : step;
            sBC[i >> 5][c] = proj[(base_row + r) * 64 + 32 + c];
        }
        __syncthreads();

        for (int i = 0; i < 64; i++) {
            int step = tc + i;
            int r = dir ? (LSEQ - 1 - step) : step;
            size_t ro = (base_row + r) * (size_t)DI + d;
            float delta = dsp[ro];
            float x     = xc[ro];
            float dx    = delta * x;
            float y = 0.0f;
#pragma unroll
            for (int s = 0; s < DS; s++) {
                float e = __expf(delta * a[s]);
                h[s] = fmaf(h[s], e, dx * sBC[i][s]);
                y = fmaf(h[s], sBC[i][16 + s], y);
            }
            float z = xz[((size_t)(b * LSEQ + r)) * 4096 + dir * 2048 + DI + d];
            float outv = (y + x * Dv) * siluf(z);
            ycat[((size_t)(b * LSEQ + r)) * 2048 + dir * DI + d] = outv;
        }
    }
}

// ---------------- dual LayerNorm: out1 = LN(in; g1,b1), out2 = LN(out1; g2,b2) ----------------
__global__ void ln_dual_k(const float* __restrict__ in,
                          const float* __restrict__ g1, const float* __restrict__ b1,
                          const float* __restrict__ g2, const float* __restrict__ b2,
                          float* __restrict__ out1, float* __restrict__ out2)
{
    __shared__ float sh[32];
    const int row = blockIdx.x;
    const int tid = threadIdx.x;
    const float* xr = in + (size_t)row * DIM;
    float v0 = xr[tid], v1 = xr[tid + 256];

    float s = v0 + v1, q = v0 * v0 + v1 * v1;
#pragma unroll
    for (int o = 16; o; o >>= 1) {
        s += __shfl_xor_sync(0xffffffffu, s, o);
        q += __shfl_xor_sync(0xffffffffu, q, o);
    }
    if ((tid & 31) == 0) { sh[tid >> 5] = s; sh[8 + (tid >> 5)] = q; }
    __syncthreads();
    if (tid == 0) {
        float S = 0.f, Q = 0.f;
        for (int i = 0; i < 8; i++) { S += sh[i]; Q += sh[8 + i]; }
        float mu = S * (1.0f / DIM);
        float var = Q * (1.0f / DIM) - mu * mu;
        sh[16] = mu; sh[17] = rsqrtf(var + 1e-5f);
    }
    __syncthreads();
    float mu = sh[16], rs = sh[17];
    float x0 = (v0 - mu) * rs * g1[tid]       + b1[tid];
    float x1 = (v1 - mu) * rs * g1[tid + 256] + b1[tid + 256];
    float* o1 = out1 + (size_t)row * DIM;
    o1[tid] = x0; o1[tid + 256] = x1;

    __syncthreads();
    s = x0 + x1; q = x0 * x0 + x1 * x1;
#pragma unroll
    for (int o = 16; o; o >>= 1) {
        s += __shfl_xor_sync(0xffffffffu, s, o);
        q += __shfl_xor_sync(0xffffffffu, q, o);
    }
    if ((tid & 31) == 0) { sh[tid >> 5] = s; sh[8 + (tid >> 5)] = q; }
    __syncthreads();
    if (tid == 0) {
        float S = 0.f, Q = 0.f;
        for (int i = 0; i < 8; i++) { S += sh[i]; Q += sh[8 + i]; }
        float mu2 = S * (1.0f / DIM);
        float var2 = Q * (1.0f / DIM) - mu2 * mu2;
        sh[16] = mu2; sh[17] = rsqrtf(var2 + 1e-5f);
    }
    __syncthreads();
    float mu2 = sh[16], rs2 = sh[17];
    float* o2 = out2 + (size_t)row * DIM;
    o2[tid]       = (x0 - mu2) * rs2 * g2[tid]       + b2[tid];
    o2[tid + 256] = (x1 - mu2) * rs2 * g2[tid + 256] + b2[tid + 256];
}

// ---------------- host launcher ----------------
extern "C" void kernel_launch(void* const* d_in, const int* in_sizes, int n_in,
                              void* d_out, int out_size)
{
    const float* tokens    = (const float*)d_in[0];
    const float* in_g      = (const float*)d_in[3];
    const float* in_b      = (const float*)d_in[4];
    const float* pos_w1    = (const float*)d_in[5];
    const float* pos_b1    = (const float*)d_in[6];
    const float* pos_w2    = (const float*)d_in[7];
    const float* pos_b2    = (const float*)d_in[8];
    const float* m_in_w    = (const float*)d_in[9];
    const float* m_conv_w  = (const float*)d_in[10];
    const float* m_conv_b  = (const float*)d_in[11];
    const float* m_xproj_w = (const float*)d_in[12];
    const float* m_dt_w    = (const float*)d_in[13];
    const float* m_dt_b    = (const float*)d_in[14];
    const float* m_A_log   = (const float*)d_in[15];
    const float* m_D       = (const float*)d_in[16];
    const float* m_out_w   = (const float*)d_in[17];
    const float* mix_w     = (const float*)d_in[18];
    const float* mix_b     = (const float*)d_in[19];
    const float* dn_g      = (const float*)d_in[20];
    const float* dn_b      = (const float*)d_in[21];
    const float* fn_g      = (const float*)d_in[22];
    const float* fn_b      = (const float*)d_in[23];
    const float* ffn_w1    = (const float*)d_in[24];
    const float* ffn_b1    = (const float*)d_in[25];
    const float* ffn_w2    = (const float*)d_in[26];
    const float* ffn_b2    = (const float*)d_in[27];
    float* out = (float*)d_out;

    float *pos_h, *pos, *pos_mix, *scan_in, *xz, *xc, *proj, *dsp, *ycat, *dmix, *dln, *lnf, *h1, *wc;
    cudaGetSymbolAddress((void**)&pos_h,   g_pos_h);
    cudaGetSymbolAddress((void**)&pos,     g_pos);
    cudaGetSymbolAddress((void**)&pos_mix, g_pos_mix);
    cudaGetSymbolAddress((void**)&scan_in, g_scan_in);
    cudaGetSymbolAddress((void**)&xz,      g_xz);
    cudaGetSymbolAddress((void**)&xc,      g_xc);
    cudaGetSymbolAddress((void**)&proj,    g_proj);
    cudaGetSymbolAddress((void**)&dsp,     g_dsp);
    cudaGetSymbolAddress((void**)&ycat,    g_ycat);
    cudaGetSymbolAddress((void**)&dmix,    g_dmix);
    cudaGetSymbolAddress((void**)&dln,     g_dln);
    cudaGetSymbolAddress((void**)&lnf,     g_lnf);
    cudaGetSymbolAddress((void**)&h1,      g_h1);
    cudaGetSymbolAddress((void**)&wc,      g_wc);

    // pos pipeline
    pos_hidden_k<<<(LSEQ * DIM) / 256, 256>>>(pos_w1, pos_b1, pos_h);
    bgemm<true, 0><<<dim3(4, 8, 1), 256>>>(pos_h, 512, 0, pos_w2, 512, 0,
                                           pos, 512, 0, pos_b2, 0, nullptr, 1,
                                           1024, 512, 512);
    // pos_mix = pos @ mix_w[:,1024:1536]^T + mix_b
    bgemm<true, 0><<<dim3(4, 8, 1), 256>>>(pos, 512, 0, mix_w + 1024, 1536, 0,
                                           pos_mix, 512, 0, mix_b, 0, nullptr, 1,
                                           1024, 512, 512);
    // Wc[dir] = mix_w[:, dir*512:(dir+1)*512] @ out_w[dir]   (512 x 1024), packed into (512, 2048)
    bgemm<false, 0><<<dim3(8, 4, 2), 256>>>(mix_w, 1536, 512, m_out_w, 1024, (long long)512 * 1024,
                                            wc, 2048, 1024, nullptr, 0, nullptr, 1,
                                            512, 1024, 512);
    // scan_in = LN(tokens) + pos
    ln_add_pos_k<<<ROWS, 256>>>(tokens, in_g, in_b, pos, scan_in);
    // xz = scan_in @ in_w_all^T   (both directions fused, N=4096)
    bgemm<true, 0><<<dim3(32, 64, 1), 256>>>(scan_in, 512, 0, m_in_w, 512, 0,
                                             xz, 4096, 0, nullptr, 0, nullptr, 1,
                                             ROWS, 4096, 512);
    // conv + silu
    conv_silu_k<<<(2 * ROWS * DI) / 256, 256>>>(xz, m_conv_w, m_conv_b, xc);
    // proj = xc @ xproj^T  (per dir)
    bgemm<true, 0><<<dim3(1, 64, 2), 256>>>(xc, 1024, (long long)ROWS * DI,
                                            m_xproj_w, 1024, (long long)64 * 1024,
                                            proj, 64, (long long)ROWS * 64,
                                            nullptr, 0, nullptr, 1,
                                            ROWS, 64, 1024);
    // dsp = softplus(dt @ dt_w^T + dt_b)  (per dir)
    bgemm<true, 3><<<dim3(8, 64, 2), 256>>>(proj, 64, (long long)ROWS * 64,
                                            m_dt_w, 32, (long long)1024 * 32,
                                            dsp, 1024, (long long)ROWS * DI,
                                            m_dt_b, 1024, nullptr, 1,
                                            ROWS, 1024, 32);
    // selective scan + gating → ycat
    scan_k<<<dim3(DI / 128, BATCH, 2), 128>>>(dsp, xc, proj, xz, m_A_log, m_D, ycat);
    // dmix = ycat @ Wc^T + pos_mix(broadcast over batch)
    bgemm<true, 4><<<dim3(4, 64, 1), 256>>>(ycat, 2048, 0, wc, 2048, 0,
                                            dmix, 512, 0, nullptr, 0, pos_mix, LSEQ,
                                            ROWS, 512, 2048);
    // dln = LN(dmix; dn),  lnf = LN(dln; fn)
    ln_dual_k<<<ROWS, 256>>>(dmix, dn_g, dn_b, fn_g, fn_b, dln, lnf);
    // h1 = gelu(lnf @ ffn_w1^T + b1)
    bgemm<true, 1><<<dim3(8, 64, 1), 256>>>(lnf, 512, 0, ffn_w1, 512, 0,
                                            h1, 1024, 0, ffn_b1, 0, nullptr, 1,
                                            ROWS, 1024, 512);
    // out = dln + h1 @ ffn_w2^T + b2
    bgemm<true, 5><<<dim3(4, 64, 1), 256>>>(h1, 1024, 0, ffn_w2, 1024, 0,
                                            out, 512, 0, ffn_b2, 0, dln, 1,
                                            ROWS, 512, 1024);
    (void)in_sizes; (void)n_in; (void)out_size;
}

// round 3
// speedup vs baseline: 1.8108x; 1.1177x over previous
#include <cuda_runtime.h>
#include <cuda_bf16.h>
#include <cstdint>
#include <math.h>

#define BATCH 8
#define LSEQ  1024
#define DIM   512
#define DI    1024
#define DS    16
#define HID   1024
#define ROWS  (BATCH*LSEQ)    // 8192

typedef __nv_bfloat16 bf16;

// ---------------- fp32 scratch ----------------
__device__ float g_pos    [LSEQ*DIM];
__device__ float g_pos_mix[LSEQ*DIM];
__device__ float g_xz     [ROWS*4096];
__device__ float g_xc     [2*ROWS*DI];
__device__ float g_proj   [2*ROWS*64];
__device__ float g_dsp    [2*ROWS*DI];
__device__ float g_dmix   [ROWS*DIM];
__device__ float g_dln    [ROWS*DIM];

// ---------------- bf16 hi/lo scratch (layout: [hi plane | lo plane]) ----------------
__device__ __align__(16) bf16 hl_scan_in[2*ROWS*DIM];
__device__ __align__(16) bf16 hl_pos_h  [2*LSEQ*DIM];
__device__ __align__(16) bf16 hl_pos    [2*LSEQ*DIM];
__device__ __align__(16) bf16 hl_w_pos2 [2*DIM*DIM];
__device__ __align__(16) bf16 hl_w_pmix [2*DIM*DIM];
__device__ __align__(16) bf16 hl_w_mixA [2*2*DIM*DIM];
__device__ __align__(16) bf16 hl_wT_out [2*2*DI*DIM];
__device__ __align__(16) bf16 hl_w_in   [2*4096*DIM];
__device__ __align__(16) bf16 hl_w_xp   [2*2*64*DI];
__device__ __align__(16) bf16 hl_w_dt   [2*2*DI*32];
__device__ __align__(16) bf16 hl_w_f1   [2*HID*DIM];
__device__ __align__(16) bf16 hl_w_f2   [2*DIM*HID];
__device__ __align__(16) bf16 hl_xc     [2*2*ROWS*DI];
__device__ __align__(16) bf16 hl_proj   [2*2*ROWS*64];
__device__ __align__(16) bf16 hl_ycat   [2*ROWS*2048];
__device__ __align__(16) bf16 hl_wc     [2*DIM*2048];
__device__ __align__(16) bf16 hl_lnf    [2*ROWS*DIM];
__device__ __align__(16) bf16 hl_h1     [2*ROWS*HID];

// ---------------- math helpers ----------------
__device__ __forceinline__ float geluf(float x) {
    return 0.5f * x * (1.0f + erff(x * 0.70710678118654752440f));
}
__device__ __forceinline__ float siluf(float x) { return x / (1.0f + __expf(-x)); }
__device__ __forceinline__ float softplusf(float x) { return (x > 20.0f) ? x : log1pf(__expf(x)); }
__device__ __forceinline__ void splitf(float v, bf16& h, bf16& l) {
    h = __float2bfloat16(v);
    l = __float2bfloat16(v - __bfloat162float(h));
}

// ---------------- PTX helpers ----------------
__device__ __forceinline__ void mma16816(float* d, const uint32_t* a, uint32_t b0, uint32_t b1) {
    asm volatile(
        "mma.sync.aligned.m16n8k16.row.col.f32.bf16.bf16.f32 "
        "{%0,%1,%2,%3},{%4,%5,%6,%7},{%8,%9},{%0,%1,%2,%3};\n"
        : "+f"(d[0]), "+f"(d[1]), "+f"(d[2]), "+f"(d[3])
        : "r"(a[0]), "r"(a[1]), "r"(a[2]), "r"(a[3]), "r"(b0), "r"(b1));
}
__device__ __forceinline__ void ldsm4(uint32_t* r, uint32_t addr) {
    asm volatile("ldmatrix.sync.aligned.m8n8.x4.shared.b16 {%0,%1,%2,%3}, [%4];\n"
                 : "=r"(r[0]), "=r"(r[1]), "=r"(r[2]), "=r"(r[3]) : "r"(addr));
}
__device__ __forceinline__ void cp16(uint32_t dst, const void* src, bool pred) {
    int sz = pred ? 16 : 0;
    asm volatile("cp.async.cg.shared.global [%0], [%1], 16, %2;\n"
                 :: "r"(dst), "l"(src), "r"(sz) : "memory");
}
__device__ __forceinline__ void cp_commit() { asm volatile("cp.async.commit_group;\n" ::: "memory"); }
__device__ __forceinline__ void cp_wait1()  { asm volatile("cp.async.wait_group 1;\n" ::: "memory"); }

// ---------------- tensor-core GEMM (pre-split bf16 hi/lo, 3-term) ----------------
// C[m,n] = sum_k A[m,k]*B[n,k];  A=(M,K), B=(N,K), both as hi/lo bf16 planes.
// EPI: 0 none, 1 gelu, 3 softplus, 4 +aux[(m%auxMod)*ldc+n], 5 +aux[m*ldc+n]
// OUT: 0 fp32 only, 1 fp32 + hi/lo, 2 hi/lo only
// M%128==0, K%32==0 required; N padded by zero-fill loads.
#define BK_STAGES 3
#define SMEM_BYTES (BK_STAGES*32768)

template<int EPI, int OUT>
__global__ void __launch_bounds__(256)
bgemm(const bf16* __restrict__ Ah, const bf16* __restrict__ Al, int lda, long long sA,
      const bf16* __restrict__ Bh, const bf16* __restrict__ Bl, int ldb, long long sB,
      float* __restrict__ C, int ldc, long long sC,
      bf16* __restrict__ Ch, long long planeC, int ldch, long long sCh,
      const float* __restrict__ bias, long long sBias,
      const float* __restrict__ aux, int auxMod,
      int M, int N, int K)
{
    extern __shared__ char smd[];
    const int zi = blockIdx.z;
    Ah += (size_t)zi * sA; Al += (size_t)zi * sA;
    Bh += (size_t)zi * sB; Bl += (size_t)zi * sB;
    if (OUT != 2) C += (size_t)zi * sC;
    if (OUT != 0) Ch += (size_t)zi * sCh;
    const float* bp = bias ? (bias + (size_t)zi * sBias) : nullptr;

    const int bm = blockIdx.y * 128;
    const int bn = blockIdx.x * 128;
    const int tid = threadIdx.x, lane = tid & 31, warp = tid >> 5;
    const int wm = warp & 1, wn = warp >> 1;

    const uint32_t smem_base = (uint32_t)__cvta_generic_to_shared(smd);

    // stage loader: A tile 128x32 (hi+lo interleaved per 128B row), B same; SW swizzle ch^(row&7)
    auto load_stage = [&](int s, int kt) {
        const int k0 = kt * 32;
        const uint32_t As = smem_base + s * 32768;
        const uint32_t Bs = As + 16384;
#pragma unroll
        for (int i = 0; i < 4; i++) {
            int lin = i * 256 + tid;
            int row = lin >> 3, ch = lin & 7;
            const bf16* srcA = ((ch & 4) ? Al : Ah) + (size_t)(bm + row) * lda + k0 + (ch & 3) * 8;
            cp16(As + row * 128 + ((ch ^ (row & 7)) * 16), srcA, true);
        }
#pragma unroll
        for (int i = 0; i < 4; i++) {
            int lin = i * 256 + tid;
            int row = lin >> 3, ch = lin & 7;
            bool ok = (bn + row) < N;
            const bf16* srcB = ((ch & 4) ? Bl : Bh) +
                               (ok ? ((size_t)(bn + row) * ldb + k0 + (ch & 3) * 8) : 0);
            cp16(Bs + row * 128 + ((ch ^ (row & 7)) * 16), srcB, ok);
        }
    };

    float acc[4][4][4];
#pragma unroll
    for (int i = 0; i < 4; i++)
#pragma unroll
        for (int j = 0; j < 4; j++)
#pragma unroll
            for (int q = 0; q < 4; q++) acc[i][j][q] = 0.0f;

    const int nk = K / 32;
    if (nk > 0) load_stage(0, 0);
    cp_commit();
    if (nk > 1) load_stage(1, 1);
    cp_commit();

    const int g  = lane >> 3;
    const int lr = lane & 7;
    const int aRow0 = wm * 64 + (g & 1) * 8 + lr;   // +mt*16
    const int bRow0 = wn * 32 + (g & 1) * 8 + lr;   // +p*16
    const int chHi  = (g >> 1);                     // + step*2 (hi), +4 for lo

    for (int kt = 0; kt < nk; kt++) {
        cp_wait1();
        __syncthreads();
        const uint32_t As = smem_base + (kt % BK_STAGES) * 32768;
        const uint32_t Bs = As + 16384;

#pragma unroll
        for (int step = 0; step < 2; step++) {
            uint32_t ah[4][4], al[4][4], bh[2][4], bl[2][4];
            const int cH = ((step * 2 + chHi) ^ lr) * 16;
            const int cL = ((4 + step * 2 + chHi) ^ lr) * 16;
#pragma unroll
            for (int mt = 0; mt < 4; mt++) {
                uint32_t rb = As + (uint32_t)(aRow0 + mt * 16) * 128;
                ldsm4(ah[mt], rb + cH);
                ldsm4(al[mt], rb + cL);
            }
#pragma unroll
            for (int p = 0; p < 2; p++) {
                uint32_t rb = Bs + (uint32_t)(bRow0 + p * 16) * 128;
                ldsm4(bh[p], rb + cH);
                ldsm4(bl[p], rb + cL);
            }
#pragma unroll
            for (int nt = 0; nt < 4; nt++) {
                const int p = nt >> 1, o = nt & 1;
                const uint32_t b0h = bh[p][o], b1h = bh[p][o + 2];
                const uint32_t b0l = bl[p][o], b1l = bl[p][o + 2];
#pragma unroll
                for (int mt = 0; mt < 4; mt++) {
                    mma16816(acc[mt][nt], ah[mt], b0h, b1h);
                    mma16816(acc[mt][nt], ah[mt], b0l, b1l);
                    mma16816(acc[mt][nt], al[mt], b0h, b1h);
                }
            }
        }
        __syncthreads();
        if (kt + 2 < nk) load_stage((kt + 2) % BK_STAGES, kt + 2);
        cp_commit();
    }

    // epilogue
    const int r_ep = lane >> 2, c_ep = lane & 3;
#pragma unroll
    for (int mt = 0; mt < 4; mt++) {
        const int m0 = bm + wm * 64 + mt * 16 + r_ep;
#pragma unroll
        for (int nt = 0; nt < 4; nt++) {
            const int n0 = bn + wn * 32 + nt * 8 + 2 * c_ep;
#pragma unroll
            for (int half = 0; half < 2; half++) {
                const int m = m0 + half * 8;
#pragma unroll
                for (int q = 0; q < 2; q++) {
                    const int n = n0 + q;
                    if (n < N) {
                        float v = acc[mt][nt][half * 2 + q];
                        if (bp) v += bp[n];
                        if (EPI == 1)      v = geluf(v);
                        else if (EPI == 3) v = softplusf(v);
                        else if (EPI == 4) v += aux[(size_t)(m % auxMod) * ldc + n];
                        else if (EPI == 5) v += aux[(size_t)m * ldc + n];
                        if (OUT != 2) C[(size_t)m * ldc + n] = v;
                        if (OUT != 0) {
                            bf16 h, l; splitf(v, h, l);
                            size_t o = (size_t)m * ldch + n;
                            Ch[o] = h; Ch[planeC + o] = l;
                        }
                    }
                }
            }
        }
    }
}

// ---------------- fp32 -> hi/lo converts ----------------
__global__ void conv_hl_k(const float* __restrict__ src, int ld, int cols, int total,
                          long long plane, bf16* __restrict__ dst)
{
    int i = blockIdx.x * 256 + threadIdx.x;
    if (i >= total) return;
    int r = i / cols, c = i - r * cols;
    float v = src[(size_t)r * ld + c];
    bf16 h, l; splitf(v, h, l);
    dst[i] = h; dst[plane + i] = l;
}
// dst (E x J) = src^T where src is (J x E)
__global__ void conv_hl_t_k(const float* __restrict__ src, int J, int E,
                            long long plane, bf16* __restrict__ dst)
{
    int i = blockIdx.x * 256 + threadIdx.x;
    if (i >= J * E) return;
    int e = i / J, j = i - e * J;
    float v = src[(size_t)j * E + e];
    bf16 h, l; splitf(v, h, l);
    dst[i] = h; dst[plane + i] = l;
}

// ---------------- positional features: gelu(pos6 @ w1^T + b1) -> hi/lo ----------------
__global__ void pos_hidden_k(const float* __restrict__ w1, const float* __restrict__ b1,
                             bf16* __restrict__ ph)
{
    int idx = blockIdx.x * 256 + threadIdx.x;
    if (idx >= LSEQ * DIM) return;
    int t = idx >> 9;
    int c = idx & 511;
    int y = t >> 5, x = t & 31;
    const float PI = 3.14159265358979323846f;
    float yy = ((y + 0.5f) / 32.0f) * 2.0f - 1.0f;
    float xx = ((x + 0.5f) / 32.0f) * 2.0f - 1.0f;
    float f2 = sinf(PI * yy), f3 = cosf(PI * yy);
    float f4 = sinf(PI * xx), f5 = cosf(PI * xx);
    const float* w = w1 + c * 6;
    float v = b1[c] + yy * w[0] + xx * w[1] + f2 * w[2] + f3 * w[3] + f4 * w[4] + f5 * w[5];
    v = geluf(v);
    bf16 h, l; splitf(v, h, l);
    ph[idx] = h; ph[LSEQ * DIM + idx] = l;
}

// ---------------- LN(tokens) + pos -> hi/lo ----------------
__global__ void ln_add_pos_k(const float* __restrict__ x,
                             const float* __restrict__ g, const float* __restrict__ b,
                             const float* __restrict__ pos, bf16* __restrict__ out)
{
    __shared__ float sh[32];
    const int row = blockIdx.x;
    const int tid = threadIdx.x;
    const float* xr = x + (size_t)row * DIM;
    float v0 = xr[tid], v1 = xr[tid + 256];

    float s = v0 + v1, q = v0 * v0 + v1 * v1;
#pragma unroll
    for (int o = 16; o; o >>= 1) {
        s += __shfl_xor_sync(0xffffffffu, s, o);
        q += __shfl_xor_sync(0xffffffffu, q, o);
    }
    if ((tid & 31) == 0) { sh[tid >> 5] = s; sh[8 + (tid >> 5)] = q; }
    __syncthreads();
    if (tid == 0) {
        float S = 0.f, Q = 0.f;
        for (int i = 0; i < 8; i++) { S += sh[i]; Q += sh[8 + i]; }
        float mu = S * (1.0f / DIM);
        float var = Q * (1.0f / DIM) - mu * mu;
        sh[16] = mu; sh[17] = rsqrtf(var + 1e-5f);
    }
    __syncthreads();
    const float mu = sh[16], rs = sh[17];
    const int t = row & (LSEQ - 1);
    const float* pr = pos + (size_t)t * DIM;
    const long long plane = (long long)ROWS * DIM;
    float r0 = (v0 - mu) * rs * g[tid]       + b[tid]       + pr[tid];
    float r1 = (v1 - mu) * rs * g[tid + 256] + b[tid + 256] + pr[tid + 256];
    bf16 h, l;
    size_t o0 = (size_t)row * DIM + tid;
    splitf(r0, h, l); out[o0] = h; out[plane + o0] = l;
    splitf(r1, h, l); out[o0 + 256] = h; out[plane + o0 + 256] = l;
}

// ---------------- causal conv (dir-aware) + SiLU -> fp32 + hi/lo ----------------
__global__ void conv_silu_k(const float* __restrict__ xz,
                            const float* __restrict__ cw, const float* __restrict__ cb,
                            float* __restrict__ xc, bf16* __restrict__ xch)
{
    size_t idx = (size_t)blockIdx.x * 256 + threadIdx.x;
    int d   = (int)(idx & 1023);
    int row = (int)((idx >> 10) & (ROWS - 1));
    int dir = (int)(idx >> 23);
    int t = row & (LSEQ - 1);
    int b = row >> 10;

    float acc = cb[dir * DI + d];
#pragma unroll
    for (int k = 0; k < 4; k++) {
        int off = dir ? (3 - k) : (k - 3);
        int tt = t + off;
        if (tt >= 0 && tt < LSEQ) {
            float v = xz[((size_t)(b * LSEQ + tt)) * 4096 + dir * 2048 + d];
            acc = fmaf(cw[(dir * DI + d) * 4 + k], v, acc);
        }
    }
    float v = siluf(acc);
    xc[idx] = v;
    bf16 h, l; splitf(v, h, l);
    xch[idx] = h; xch[(size_t)2 * ROWS * DI + idx] = l;
}

// ---------------- selective scan -> ycat hi/lo ----------------
__global__ void scan_k(const float* __restrict__ dsp, const float* __restrict__ xc,
                       const float* __restrict__ proj, const float* __restrict__ xz,
                       const float* __restrict__ A_log, const float* __restrict__ Dp,
                       bf16* __restrict__ ycat)
{
    const int dir = blockIdx.z;
    const int b   = blockIdx.y;
    const int d   = blockIdx.x * 128 + threadIdx.x;

    float a[DS];
#pragma unroll
    for (int s = 0; s < DS; s++)
        a[s] = -expf(A_log[((size_t)dir * DI + d) * DS + s]);
    const float Dv = Dp[dir * DI + d];

    float h[DS];
#pragma unroll
    for (int s = 0; s < DS; s++) h[s] = 0.0f;

    const size_t base_row = (size_t)dir * ROWS + (size_t)b * LSEQ;
    const long long plane = (long long)ROWS * 2048;
    __shared__ float sBC[64][32];

    for (int tc = 0; tc < LSEQ; tc += 64) {
        __syncthreads();
        for (int i = threadIdx.x; i < 64 * 32; i += 128) {
            int step = tc + (i >> 5);
            int c = i & 31;
            int r = dir ? (LSEQ - 1 - step) : step;
            sBC[i >> 5][c] = proj[(base_row + r) * 64 + 32 + c];
        }
        __syncthreads();

        for (int i = 0; i < 64; i++) {
            int step = tc + i;
            int r = dir ? (LSEQ - 1 - step) : step;
            size_t ro = (base_row + r) * (size_t)DI + d;
            float delta = dsp[ro];
            float x     = xc[ro];
            float dx    = delta * x;
            float y = 0.0f;
#pragma unroll
            for (int s = 0; s < DS; s++) {
                float e = __expf(delta * a[s]);
                h[s] = fmaf(h[s], e, dx * sBC[i][s]);
                y = fmaf(h[s], sBC[i][16 + s], y);
            }
            float z = xz[((size_t)(b * LSEQ + r)) * 4096 + dir * 2048 + DI + d];
            float outv = (y + x * Dv) * siluf(z);
            bf16 hh, ll; splitf(outv, hh, ll);
            size_t oo = ((size_t)(b * LSEQ + r)) * 2048 + dir * DI + d;
            ycat[oo] = hh; ycat[plane + oo] = ll;
        }
    }
}

// ---------------- dual LayerNorm: dln = LN(in), lnf(hi/lo) = LN(dln) ----------------
__global__ void ln_dual_k(const float* __restrict__ in,
                          const float* __restrict__ g1, const float* __restrict__ b1,
                          const float* __restrict__ g2, const float* __restrict__ b2,
                          float* __restrict__ out1, bf16* __restrict__ out2)
{
    __shared__ float sh[32];
    const int row = blockIdx.x;
    const int tid = threadIdx.x;
    const float* xr = in + (size_t)row * DIM;
    float v0 = xr[tid], v1 = xr[tid + 256];

    float s = v0 + v1, q = v0 * v0 + v1 * v1;
#pragma unroll
    for (int o = 16; o; o >>= 1) {
        s += __shfl_xor_sync(0xffffffffu, s, o);
        q += __shfl_xor_sync(0xffffffffu, q, o);
    }
    if ((tid & 31) == 0) { sh[tid >> 5] = s; sh[8 + (tid >> 5)] = q; }
    __syncthreads();
    if (tid == 0) {
        float S = 0.f, Q = 0.f;
        for (int i = 0; i < 8; i++) { S += sh[i]; Q += sh[8 + i]; }
        float mu = S * (1.0f / DIM);
        float var = Q * (1.0f / DIM) - mu * mu;
        sh[16] = mu; sh[17] = rsqrtf(var + 1e-5f);
    }
    __syncthreads();
    float mu = sh[16], rs = sh[17];
    float x0 = (v0 - mu) * rs * g1[tid]       + b1[tid];
    float x1 = (v1 - mu) * rs * g1[tid + 256] + b1[tid + 256];
    float* o1 = out1 + (size_t)row * DIM;
    o1[tid] = x0; o1[tid + 256] = x1;

    __syncthreads();
    s = x0 + x1; q = x0 * x0 + x1 * x1;
#pragma unroll
    for (int o = 16; o; o >>= 1) {
        s += __shfl_xor_sync(0xffffffffu, s, o);
        q += __shfl_xor_sync(0xffffffffu, q, o);
    }
    if ((tid & 31) == 0) { sh[tid >> 5] = s; sh[8 + (tid >> 5)] = q; }
    __syncthreads();
    if (tid == 0) {
        float S = 0.f, Q = 0.f;
        for (int i = 0; i < 8; i++) { S += sh[i]; Q += sh[8 + i]; }
        float mu2 = S * (1.0f / DIM);
        float var2 = Q * (1.0f / DIM) - mu2 * mu2;
        sh[16] = mu2; sh[17] = rsqrtf(var2 + 1e-5f);
    }
    __syncthreads();
    float mu2 = sh[16], rs2 = sh[17];
    const long long plane = (long long)ROWS * DIM;
    float y0 = (x0 - mu2) * rs2 * g2[tid]       + b2[tid];
    float y1 = (x1 - mu2) * rs2 * g2[tid + 256] + b2[tid + 256];
    bf16 h, l;
    size_t o0 = (size_t)row * DIM + tid;
    splitf(y0, h, l); out2[o0] = h; out2[plane + o0] = l;
    splitf(y1, h, l); out2[o0 + 256] = h; out2[plane + o0 + 256] = l;
}

// ---------------- host launcher ----------------
extern "C" void kernel_launch(void* const* d_in, const int* in_sizes, int n_in,
                              void* d_out, int out_size)
{
    const float* tokens    = (const float*)d_in[0];
    const float* in_g      = (const float*)d_in[3];
    const float* in_b      = (const float*)d_in[4];
    const float* pos_w1    = (const float*)d_in[5];
    const float* pos_b1    = (const float*)d_in[6];
    const float* pos_w2    = (const float*)d_in[7];
    const float* pos_b2    = (const float*)d_in[8];
    const float* m_in_w    = (const float*)d_in[9];
    const float* m_conv_w  = (const float*)d_in[10];
    const float* m_conv_b  = (const float*)d_in[11];
    const float* m_xproj_w = (const float*)d_in[12];
    const float* m_dt_w    = (const float*)d_in[13];
    const float* m_dt_b    = (const float*)d_in[14];
    const float* m_A_log   = (const float*)d_in[15];
    const float* m_D       = (const float*)d_in[16];
    const float* m_out_w   = (const float*)d_in[17];
    const float* mix_w     = (const float*)d_in[18];
    const float* mix_b     = (const float*)d_in[19];
    const float* dn_g      = (const float*)d_in[20];
    const float* dn_b      = (const float*)d_in[21];
    const float* fn_g      = (const float*)d_in[22];
    const float* fn_b      = (const float*)d_in[23];
    const float* ffn_w1    = (const float*)d_in[24];
    const float* ffn_b1    = (const float*)d_in[25];
    const float* ffn_w2    = (const float*)d_in[26];
    const float* ffn_b2    = (const float*)d_in[27];
    float* out = (float*)d_out;

    float *pos, *pos_mix, *xz, *xc, *proj, *dsp, *dmix, *dln;
    bf16 *sin_hl, *posh_hl, *pos_hl, *wpos2, *wpmix, *wmixA, *wTout, *win, *wxp, *wdt, *wf1, *wf2;
    bf16 *xc_hl, *proj_hl, *ycat_hl, *wc_hl, *lnf_hl, *h1_hl;
    cudaGetSymbolAddress((void**)&pos,     g_pos);
    cudaGetSymbolAddress((void**)&pos_mix, g_pos_mix);
    cudaGetSymbolAddress((void**)&xz,      g_xz);
    cudaGetSymbolAddress((void**)&xc,      g_xc);
    cudaGetSymbolAddress((void**)&proj,    g_proj);
    cudaGetSymbolAddress((void**)&dsp,     g_dsp);
    cudaGetSymbolAddress((void**)&dmix,    g_dmix);
    cudaGetSymbolAddress((void**)&dln,     g_dln);
    cudaGetSymbolAddress((void**)&sin_hl,  hl_scan_in);
    cudaGetSymbolAddress((void**)&posh_hl, hl_pos_h);
    cudaGetSymbolAddress((void**)&pos_hl,  hl_pos);
    cudaGetSymbolAddress((void**)&wpos2,   hl_w_pos2);
    cudaGetSymbolAddress((void**)&wpmix,   hl_w_pmix);
    cudaGetSymbolAddress((void**)&wmixA,   hl_w_mixA);
    cudaGetSymbolAddress((void**)&wTout,   hl_wT_out);
    cudaGetSymbolAddress((void**)&win,     hl_w_in);
    cudaGetSymbolAddress((void**)&wxp,     hl_w_xp);
    cudaGetSymbolAddress((void**)&wdt,     hl_w_dt);
    cudaGetSymbolAddress((void**)&wf1,     hl_w_f1);
    cudaGetSymbolAddress((void**)&wf2,     hl_w_f2);
    cudaGetSymbolAddress((void**)&xc_hl,   hl_xc);
    cudaGetSymbolAddress((void**)&proj_hl, hl_proj);
    cudaGetSymbolAddress((void**)&ycat_hl, hl_ycat);
    cudaGetSymbolAddress((void**)&wc_hl,   hl_wc);
    cudaGetSymbolAddress((void**)&lnf_hl,  hl_lnf);
    cudaGetSymbolAddress((void**)&h1_hl,   hl_h1);

    cudaFuncSetAttribute(bgemm<0,0>, cudaFuncAttributeMaxDynamicSharedMemorySize, SMEM_BYTES);
    cudaFuncSetAttribute(bgemm<0,1>, cudaFuncAttributeMaxDynamicSharedMemorySize, SMEM_BYTES);
    cudaFuncSetAttribute(bgemm<0,2>, cudaFuncAttributeMaxDynamicSharedMemorySize, SMEM_BYTES);
    cudaFuncSetAttribute(bgemm<3,0>, cudaFuncAttributeMaxDynamicSharedMemorySize, SMEM_BYTES);
    cudaFuncSetAttribute(bgemm<4,0>, cudaFuncAttributeMaxDynamicSharedMemorySize, SMEM_BYTES);
    cudaFuncSetAttribute(bgemm<1,2>, cudaFuncAttributeMaxDynamicSharedMemorySize, SMEM_BYTES);
    cudaFuncSetAttribute(bgemm<5,0>, cudaFuncAttributeMaxDynamicSharedMemorySize, SMEM_BYTES);

    // ---- weight converts (independent) ----
    conv_hl_k<<<1024, 256>>>(pos_w2,       512, 512, 512*512, 512*512, wpos2);
    conv_hl_k<<<1024, 256>>>(mix_w + 1024, 1536, 512, 512*512, 512*512, wpmix);
    conv_hl_k<<<1024, 256>>>(mix_w,        1536, 512, 512*512, (long long)2*512*512, wmixA);
    conv_hl_k<<<1024, 256>>>(mix_w + 512,  1536, 512, 512*512, (long long)2*512*512, wmixA + 512*512);
    conv_hl_t_k<<<2048, 256>>>(m_out_w,            512, 1024, (long long)2*1024*512, wTout);
    conv_hl_t_k<<<2048, 256>>>(m_out_w + 512*1024, 512, 1024, (long long)2*1024*512, wTout + 1024*512);
    conv_hl_k<<<8192, 256>>>(m_in_w,    512, 512, 4096*512, (long long)4096*512, win);
    conv_hl_k<<<512,  256>>>(m_xproj_w, 1024, 1024, 128*1024, (long long)128*1024, wxp);
    conv_hl_k<<<256,  256>>>(m_dt_w,    32, 32, 2048*32, (long long)2048*32, wdt);
    conv_hl_k<<<2048, 256>>>(ffn_w1,    512, 512, 1024*512, (long long)1024*512, wf1);
    conv_hl_k<<<2048, 256>>>(ffn_w2,    1024, 1024, 512*1024, (long long)512*1024, wf2);

    // ---- pos pipeline ----
    pos_hidden_k<<<2048, 256>>>(pos_w1, pos_b1, posh_hl);
    // pos = gelu_h @ pos_w2^T + b2  (fp32 + hi/lo)
    bgemm<0,1><<<dim3(4,8,1), 256, SMEM_BYTES>>>(
        posh_hl, posh_hl + LSEQ*DIM, 512, 0,  wpos2, wpos2 + 512*512, 512, 0,
        pos, 512, 0,  pos_hl, (long long)LSEQ*DIM, 512, 0,
        pos_b2, 0, nullptr, 1, LSEQ, 512, 512);
    // pos_mix = pos @ mix_w[:,1024:1536]^T + mix_b
    bgemm<0,0><<<dim3(4,8,1), 256, SMEM_BYTES>>>(
        pos_hl, pos_hl + LSEQ*DIM, 512, 0,  wpmix, wpmix + 512*512, 512, 0,
        pos_mix, 512, 0,  nullptr, 0, 0, 0,
        mix_b, 0, nullptr, 1, LSEQ, 512, 512);
    // Wc[dir] = mix_w_slice @ out_w[dir]  -> hi/lo only, packed (512, 2048)
    bgemm<0,2><<<dim3(8,4,2), 256, SMEM_BYTES>>>(
        wmixA, wmixA + (long long)2*512*512, 512, (long long)512*512,
        wTout, wTout + (long long)2*1024*512, 512, (long long)1024*512,
        nullptr, 0, 0,
        wc_hl, (long long)512*2048, 2048, 1024,
        nullptr, 0, nullptr, 1, 512, 1024, 512);
    // scan_in(hi/lo) = LN(tokens) + pos
    ln_add_pos_k<<<ROWS, 256>>>(tokens, in_g, in_b, pos, sin_hl);
    // xz = scan_in @ in_w^T (fused dirs, N=4096)
    bgemm<0,0><<<dim3(32,64,1), 256, SMEM_BYTES>>>(
        sin_hl, sin_hl + (long long)ROWS*DIM, 512, 0,
        win, win + (long long)4096*512, 512, 0,
        xz, 4096, 0, nullptr, 0, 0, 0,
        nullptr, 0, nullptr, 1, ROWS, 4096, 512);
    // conv + silu (fp32 + hi/lo)
    conv_silu_k<<<(2*ROWS*DI)/256, 256>>>(xz, m_conv_w, m_conv_b, xc, xc_hl);
    // proj = xc @ xproj^T per dir (fp32 + hi/lo)
    bgemm<0,1><<<dim3(1,64,2), 256, SMEM_BYTES>>>(
        xc_hl, xc_hl + (long long)2*ROWS*DI, 1024, (long long)ROWS*DI,
        wxp, wxp + (long long)128*1024, 1024, (long long)64*1024,
        proj, 64, (long long)ROWS*64,
        proj_hl, (long long)2*ROWS*64, 64, (long long)ROWS*64,
        nullptr, 0, nullptr, 1, ROWS, 64, 1024);
    // dsp = softplus(dt @ dt_w^T + dt_b) per dir
    bgemm<3,0><<<dim3(8,64,2), 256, SMEM_BYTES>>>(
        proj_hl, proj_hl + (long long)2*ROWS*64, 64, (long long)ROWS*64,
        wdt, wdt + (long long)2048*32, 32, (long long)1024*32,
        dsp, 1024, (long long)ROWS*DI, nullptr, 0, 0, 0,
        m_dt_b, 1024, nullptr, 1, ROWS, 1024, 32);
    // selective scan + gating -> ycat(hi/lo)
    scan_k<<<dim3(DI/128, BATCH, 2), 128>>>(dsp, xc, proj, xz, m_A_log, m_D, ycat_hl);
    // dmix = ycat @ Wc^T + pos_mix(broadcast)
    bgemm<4,0><<<dim3(4,64,1), 256, SMEM_BYTES>>>(
        ycat_hl, ycat_hl + (long long)ROWS*2048, 2048, 0,
        wc_hl, wc_hl + (long long)512*2048, 2048, 0,
        dmix, 512, 0, nullptr, 0, 0, 0,
        nullptr, 0, pos_mix, LSEQ, ROWS, 512, 2048);
    // dln = LN(dmix), lnf(hi/lo) = LN(dln)
    ln_dual_k<<<ROWS, 256>>>(dmix, dn_g, dn_b, fn_g, fn_b, dln, lnf_hl);
    // h1(hi/lo) = gelu(lnf @ ffn_w1^T + b1)
    bgemm<1,2><<<dim3(8,64,1), 256, SMEM_BYTES>>>(
        lnf_hl, lnf_hl + (long long)ROWS*DIM, 512, 0,
        wf1, wf1 + (long long)1024*512, 512, 0,
        nullptr, 1024, 0,
        h1_hl, (long long)ROWS*HID, 1024, 0,
        ffn_b1, 0, nullptr, 1, ROWS, 1024, 512);
    // out = dln + h1 @ ffn_w2^T + b2
    bgemm<5,0><<<dim3(4,64,1), 256, SMEM_BYTES>>>(
        h1_hl, h1_hl + (long long)ROWS*HID, 1024, 0,
        wf2, wf2 + (long long)512*1024, 1024, 0,
        out, 512, 0, nullptr, 0, 0, 0,
        ffn_b2, 0, dln, 1, ROWS, 512, 1024);

    (void)in_sizes; (void)n_in; (void)out_size;
}